// round 14
// baseline (speedup 1.0000x reference)
#include <cuda_runtime.h>
#include <cuda_fp16.h>
#include <cstdint>

#define NN 4096   // nodes
#define DD 128    // embed dim
#define RR 8      // relations
#define OO 128    // out dim
#define BB 4096   // batch
#define ZSPLIT 8  // k-splits in s_gemm

// Scratch: W[r][n][o] = (E @ K[r])[n][o], fp16, 8 MB.
__device__ __half d_W16[RR * (size_t)NN * OO];
// Scratch: partial S per k-split (rank-major), fp32, 16 MB.
__device__ float d_Spart[ZSPLIT * (size_t)NN * OO];
// Scratch: S[rank][o], fp32, 2 MB.
__device__ float d_S[(size_t)NN * OO];
// Compaction of referenced nodes:
__device__ int d_list[NN];    // rank -> node (padded with 0)
__device__ int d_rank[NN];    // node -> rank (valid for referenced nodes)
__device__ int d_count;       // number of unique referenced nodes

// ---------------------------------------------------------------------------
// MMA helpers
// ---------------------------------------------------------------------------
__device__ __forceinline__ uint32_t smaddr(const void* p) {
    return (uint32_t)__cvta_generic_to_shared(p);
}
__device__ __forceinline__ void ldsm_x4(uint32_t (&r)[4], uint32_t addr) {
    asm volatile("ldmatrix.sync.aligned.m8n8.x4.shared.b16 {%0,%1,%2,%3}, [%4];"
        : "=r"(r[0]), "=r"(r[1]), "=r"(r[2]), "=r"(r[3]) : "r"(addr));
}
__device__ __forceinline__ void ldsm_x4t(uint32_t (&r)[4], uint32_t addr) {
    asm volatile("ldmatrix.sync.aligned.m8n8.x4.trans.shared.b16 {%0,%1,%2,%3}, [%4];"
        : "=r"(r[0]), "=r"(r[1]), "=r"(r[2]), "=r"(r[3]) : "r"(addr));
}
__device__ __forceinline__ void mma_16816(float (&c)[4], const uint32_t (&a)[4],
                                          const uint32_t b0, const uint32_t b1) {
    asm volatile(
        "mma.sync.aligned.m16n8k16.row.col.f32.f16.f16.f32 "
        "{%0,%1,%2,%3}, {%4,%5,%6,%7}, {%8,%9}, {%0,%1,%2,%3};"
        : "+f"(c[0]), "+f"(c[1]), "+f"(c[2]), "+f"(c[3])
        : "r"(a[0]), "r"(a[1]), "r"(a[2]), "r"(a[3]), "r"(b0), "r"(b1));
}
__device__ __forceinline__ void cpa16(uint32_t s, const void* g) {
    asm volatile("cp.async.cg.shared.global [%0], [%1], 16;" :: "r"(s), "l"(g));
}
#define CPA_COMMIT() asm volatile("cp.async.commit_group;" ::: "memory")
#define CPA_WAIT0()  asm volatile("cp.async.wait_group 0;" ::: "memory")

// ---------------------------------------------------------------------------
// Kernel P: mark referenced nodes, prefix-scan, compact. 1 CTA, 1024 thr.
// ---------------------------------------------------------------------------
__global__ __launch_bounds__(1024) void prep_kernel(
    const int* __restrict__ hidx, const int* __restrict__ tidx)
{
    __shared__ int fl[NN];        // 16 KB
    __shared__ int wsum[32];
    const int t = threadIdx.x;
    const int lane = t & 31, wid = t >> 5;

    ((int4*)fl)[t] = make_int4(0, 0, 0, 0);
    __syncthreads();
#pragma unroll
    for (int j = 0; j < 4; j++) {
        int id = t + j * 1024;
        fl[hidx[id]] = 1;
        fl[tidx[id]] = 1;
    }
    __syncthreads();

    int f[4], s = 0;
#pragma unroll
    for (int j = 0; j < 4; j++) { f[j] = fl[t * 4 + j]; s += f[j]; }

    int incl = s;
#pragma unroll
    for (int off = 1; off < 32; off <<= 1) {
        int v = __shfl_up_sync(0xffffffffu, incl, off);
        if (lane >= off) incl += v;
    }
    if (lane == 31) wsum[wid] = incl;
    __syncthreads();
    if (wid == 0) {
        int w = wsum[lane];
#pragma unroll
        for (int off = 1; off < 32; off <<= 1) {
            int v = __shfl_up_sync(0xffffffffu, w, off);
            if (lane >= off) w += v;
        }
        wsum[lane] = w;
    }
    __syncthreads();

    int run = (wid ? wsum[wid - 1] : 0) + incl - s;
#pragma unroll
    for (int j = 0; j < 4; j++) {
        if (f[j]) {
            int n = t * 4 + j;
            d_list[run] = n;
            d_rank[n] = run;
            run++;
        }
    }
    const int total = wsum[31];
    if (t == 0) d_count = total;
    for (int i = total + t; i < NN; i += 1024) d_list[i] = 0;
}

// ---------------------------------------------------------------------------
// Single-shot MROWSx128x128 fp16 MMA core (w_gemm / out_gemm).
// ---------------------------------------------------------------------------
#define STR 136                       // halves per smem row (128 + 8 pad)

template<int MROWS>
__device__ __forceinline__ void wo_core(
    const float* __restrict__ Ag, const float* __restrict__ Bg,
    char* dsm, float (&acc)[MROWS / 32][4][4])
{
    constexpr int MF = MROWS / 32;
    const int t = threadIdx.x;
    const uint32_t sb = smaddr(dsm);
    char* As = dsm;
    char* Bs = dsm + MROWS * STR * 2;
    const uint32_t AOFF = sb, BOFF = sb + MROWS * STR * 2;

#pragma unroll
    for (int j = 0; j < MROWS / 8; j++) {
        int id = t + j * 256;
        int row = id >> 5, c4 = id & 31;
        float4 v = *(const float4*)(Ag + (size_t)row * 128 + c4 * 4);
        __half2 h0 = __floats2half2_rn(v.x, v.y);
        __half2 h1 = __floats2half2_rn(v.z, v.w);
        uint2 u; u.x = *(uint32_t*)&h0; u.y = *(uint32_t*)&h1;
        *(uint2*)(As + row * STR * 2 + c4 * 8) = u;
    }
#pragma unroll
    for (int j = 0; j < 16; j++) {
        int id = t + j * 256;
        int row = id >> 5, c4 = id & 31;
        float4 v = *(const float4*)(Bg + (size_t)row * 128 + c4 * 4);
        __half2 h0 = __floats2half2_rn(v.x, v.y);
        __half2 h1 = __floats2half2_rn(v.z, v.w);
        uint2 u; u.x = *(uint32_t*)&h0; u.y = *(uint32_t*)&h1;
        *(uint2*)(Bs + row * STR * 2 + c4 * 8) = u;
    }
    __syncthreads();

    const int warp = t >> 5, lane = t & 31;
    const int wm = warp >> 2, wn = warp & 3;

    uint32_t a_off[MF], b_off[2];
#pragma unroll
    for (int mf = 0; mf < MF; mf++) {
        int row = wm * (MROWS / 2) + mf * 16 + (lane & 15);
        int col = ((lane >> 4) << 3);
        a_off[mf] = (uint32_t)(row * STR * 2 + col * 2);
    }
#pragma unroll
    for (int nf2 = 0; nf2 < 2; nf2++) {
        int row = (lane & 15);
        int col = wn * 32 + nf2 * 16 + ((lane >> 4) << 3);
        b_off[nf2] = (uint32_t)(row * STR * 2 + col * 2);
    }

#pragma unroll
    for (int ks = 0; ks < 8; ks++) {
        uint32_t af[MF][4], bf[2][4];
#pragma unroll
        for (int mf = 0; mf < MF; mf++)
            ldsm_x4(af[mf], AOFF + a_off[mf] + ks * 32);
#pragma unroll
        for (int nf2 = 0; nf2 < 2; nf2++)
            ldsm_x4t(bf[nf2], BOFF + b_off[nf2] + ks * 16 * STR * 2);
#pragma unroll
        for (int mf = 0; mf < MF; mf++)
#pragma unroll
            for (int nf = 0; nf < 4; nf++)
                mma_16816(acc[mf][nf], af[mf], bf[nf >> 1][(nf & 1) * 2],
                          bf[nf >> 1][(nf & 1) * 2 + 1]);
    }
}

// ---------------------------------------------------------------------------
// Kernel 1: W16[r] = fp16(E @ K[r]).  grid (32 m-tiles, 8 relations), 256 thr.
// ---------------------------------------------------------------------------
#define W_SMEM (2 * 128 * STR * 2)   // 69632 B

__global__ __launch_bounds__(256, 2) void w_gemm(
    const float* __restrict__ emb, const float* __restrict__ relk)
{
    extern __shared__ __align__(128) char dsm[];
    const int m0 = blockIdx.x * 128;
    const int r = blockIdx.y;

    float acc[4][4][4];
#pragma unroll
    for (int mf = 0; mf < 4; mf++)
#pragma unroll
        for (int nf = 0; nf < 4; nf++)
#pragma unroll
            for (int v = 0; v < 4; v++) acc[mf][nf][v] = 0.f;

    wo_core<128>(emb + (size_t)m0 * DD, relk + (size_t)r * DD * OO, dsm, acc);

    const int warp = threadIdx.x >> 5, lane = threadIdx.x & 31;
    const int wm = warp >> 2, wn = warp & 3;
    __half* Wr = d_W16 + (size_t)r * NN * OO;
    const int rbase = m0 + wm * 64 + (lane >> 2);
    const int cbase = wn * 32 + (lane & 3) * 2;
#pragma unroll
    for (int mf = 0; mf < 4; mf++)
#pragma unroll
        for (int nf = 0; nf < 4; nf++) {
            int rr = rbase + mf * 16, cc = cbase + nf * 8;
            *(__half2*)(Wr + (size_t)rr * OO + cc) =
                __floats2half2_rn(acc[mf][nf][0], acc[mf][nf][1]);
            *(__half2*)(Wr + (size_t)(rr + 8) * OO + cc) =
                __floats2half2_rn(acc[mf][nf][2], acc[mf][nf][3]);
        }
}

// ---------------------------------------------------------------------------
// Kernel 2: Spart[z][rank][o] = sum_r sum_{k in z} adj[r, list[rank], k] W[r][k][o]
// Row-gathered A; tiles beyond d_count exit early (CTA-uniform guard).
// grid (32 m-tiles, 8 z-splits), 256 thr, double-buffered, cp.async B.
// ---------------------------------------------------------------------------
#define BM 128
#define BK 64
#define KRANGE (NN / ZSPLIT)      // 512 k per CTA per relation
#define QITERS (RR * KRANGE / BK) // 64 chunks
#define ASTR (BK + 8)
#define BSTR (OO + 8)
#define A_STAGE (BM * ASTR * 2)   // 18432 B
#define B_STAGE (BK * BSTR * 2)   // 17408 B
#define SG_SMEM (2 * A_STAGE + 2 * B_STAGE)   // 71680 B

__global__ __launch_bounds__(256, 2) void s_gemm(const float* __restrict__ adj)
{
    const int m0 = blockIdx.x * BM;
    if (m0 >= d_count) return;                     // tile fully past unique rows

    extern __shared__ __align__(128) char dsm[];
    __shared__ int rows_s[BM];
    const uint32_t sb = smaddr(dsm);
    const int t = threadIdx.x;
    const int z = blockIdx.y;
    const int kz = z * KRANGE;

    if (t < BM) rows_s[t] = d_list[m0 + t];
    __syncthreads();

    const uint32_t AOFF[2] = { sb, sb + A_STAGE };
    char* const ABASE[2] = { dsm, dsm + A_STAGE };
    const uint32_t BOFF[2] = { sb + 2 * A_STAGE, sb + 2 * A_STAGE + B_STAGE };

    const float* aptr[8]; uint32_t ast[8];
#pragma unroll
    for (int j = 0; j < 8; j++) {
        int id = t + j * 256;
        int arow = id >> 4, ac4 = id & 15;
        aptr[j] = adj + (size_t)rows_s[arow] * NN + kz + ac4 * 4;
        ast[j] = (uint32_t)(arow * ASTR * 2 + ac4 * 8);
    }
    const __half* bgp[4]; uint32_t bst[4];
#pragma unroll
    for (int j = 0; j < 4; j++) {
        int id = t + j * 256;
        int brow = id >> 4, bc8 = id & 15;
        bgp[j] = d_W16 + (size_t)(kz + brow) * OO + bc8 * 8;
        bst[j] = (uint32_t)(brow * BSTR * 2 + bc8 * 16);
    }

    const int warp = t >> 5, lane = t & 31;
    const int wm = warp >> 2, wn = warp & 3;

    float acc[4][4][4];
#pragma unroll
    for (int mf = 0; mf < 4; mf++)
#pragma unroll
        for (int nf = 0; nf < 4; nf++)
#pragma unroll
            for (int v = 0; v < 4; v++) acc[mf][nf][v] = 0.f;

    uint32_t a_off[4], b_off[2];
#pragma unroll
    for (int mf = 0; mf < 4; mf++) {
        int row = wm * 64 + mf * 16 + (lane & 15);
        int col = ((lane >> 4) << 3);
        a_off[mf] = (uint32_t)(row * ASTR * 2 + col * 2);
    }
#pragma unroll
    for (int nf2 = 0; nf2 < 2; nf2++) {
        int row = (lane & 15);
        int col = wn * 32 + nf2 * 16 + ((lane >> 4) << 3);
        b_off[nf2] = (uint32_t)(row * BSTR * 2 + col * 2);
    }

    // per-chunk uniform offsets: q -> (r = q>>3, kc = q&7)
    auto QA = [](int q) -> size_t {
        return ((size_t)(q >> 3) * (size_t)NN * NN) + (size_t)(q & 7) * BK;
    };
    auto QB = [](int q) -> size_t {
        return ((size_t)(q >> 3) * (size_t)NN * OO) + (size_t)(q & 7) * BK * OO;
    };

    float4 areg[8];

    // prologue: chunk 0 -> stage 0
#pragma unroll
    for (int j = 0; j < 8; j++) areg[j] = *(const float4*)aptr[j];
#pragma unroll
    for (int j = 0; j < 8; j++) {
        __half2 h0 = __floats2half2_rn(areg[j].x, areg[j].y);
        __half2 h1 = __floats2half2_rn(areg[j].z, areg[j].w);
        uint2 u; u.x = *(uint32_t*)&h0; u.y = *(uint32_t*)&h1;
        *(uint2*)(ABASE[0] + ast[j]) = u;
    }
#pragma unroll
    for (int j = 0; j < 4; j++) cpa16(BOFF[0] + bst[j], bgp[j]);
    CPA_COMMIT();
    {
        const size_t o1 = QA(1);
#pragma unroll
        for (int j = 0; j < 8; j++) areg[j] = *(const float4*)(aptr[j] + o1);
    }
    CPA_WAIT0();
    __syncthreads();

    for (int q = 0; q < QITERS; q++) {
        const int s = q & 1, ns = s ^ 1;

        if (q + 1 < QITERS) {
#pragma unroll
            for (int j = 0; j < 8; j++) {
                __half2 h0 = __floats2half2_rn(areg[j].x, areg[j].y);
                __half2 h1 = __floats2half2_rn(areg[j].z, areg[j].w);
                uint2 u; u.x = *(uint32_t*)&h0; u.y = *(uint32_t*)&h1;
                *(uint2*)(ABASE[ns] + ast[j]) = u;
            }
            const size_t ob = QB(q + 1);
#pragma unroll
            for (int j = 0; j < 4; j++) cpa16(BOFF[ns] + bst[j], bgp[j] + ob);
            CPA_COMMIT();
        }
        if (q + 2 < QITERS) {
            const size_t oa = QA(q + 2);
#pragma unroll
            for (int j = 0; j < 8; j++) areg[j] = *(const float4*)(aptr[j] + oa);
        }

#pragma unroll
        for (int ks = 0; ks < 4; ks++) {
            uint32_t af[4][4], bf[2][4];
#pragma unroll
            for (int mf = 0; mf < 4; mf++)
                ldsm_x4(af[mf], AOFF[s] + a_off[mf] + ks * 32);
#pragma unroll
            for (int nf2 = 0; nf2 < 2; nf2++)
                ldsm_x4t(bf[nf2], BOFF[s] + b_off[nf2] + ks * 16 * BSTR * 2);
#pragma unroll
            for (int mf = 0; mf < 4; mf++)
#pragma unroll
                for (int nf = 0; nf < 4; nf++)
                    mma_16816(acc[mf][nf], af[mf], bf[nf >> 1][(nf & 1) * 2],
                              bf[nf >> 1][(nf & 1) * 2 + 1]);
        }

        if (q + 1 < QITERS) CPA_WAIT0();
        __syncthreads();
    }

    float* Sp = d_Spart + (size_t)z * NN * OO;
    const int rbase = m0 + wm * 64 + (lane >> 2);
    const int cbase = wn * 32 + (lane & 3) * 2;
#pragma unroll
    for (int mf = 0; mf < 4; mf++)
#pragma unroll
        for (int nf = 0; nf < 4; nf++) {
            int rr = rbase + mf * 16, cc = cbase + nf * 8;
            *(float2*)(Sp + (size_t)rr * OO + cc) =
                make_float2(acc[mf][nf][0], acc[mf][nf][1]);
            *(float2*)(Sp + (size_t)(rr + 8) * OO + cc) =
                make_float2(acc[mf][nf][2], acc[mf][nf][3]);
        }
}

// ---------------------------------------------------------------------------
// Kernel 3: S[rank] = sum_z Spart[z][rank] for rank < count.
// ---------------------------------------------------------------------------
__global__ __launch_bounds__(512) void reduce_kernel()
{
    const size_t i = (size_t)blockIdx.x * 512 + threadIdx.x;   // float4 index
    if ((int)(i >> 5) >= d_count) return;                      // 32 float4/row
    const float4* p = (const float4*)d_Spart + i;
    float4 s = p[0];
#pragma unroll
    for (int zz = 1; zz < ZSPLIT; zz++) {
        float4 v = p[(size_t)zz * (NN * OO / 4)];
        s.x += v.x; s.y += v.y; s.z += v.z; s.w += v.w;
    }
    ((float4*)d_S)[i] = s;
}

// ---------------------------------------------------------------------------
// Kernel 4: out[m][o] = ([he;te] @ SK)[m][o] + S[rank[idx[m]]][o]
// 32-row tiles: grid 256 CTAs, 256 threads.
// ---------------------------------------------------------------------------
#define O_SMEM ((32 + 128) * STR * 2)   // 43520 B

__global__ __launch_bounds__(256) void out_gemm(
    const float* __restrict__ head_e, const float* __restrict__ tail_e,
    const int* __restrict__ head_idx, const int* __restrict__ tail_idx,
    const float* __restrict__ sk, float* __restrict__ out)
{
    extern __shared__ __align__(128) char dsm[];
    const int m0 = blockIdx.x * 32;
    const int branch = (m0 >= BB);
    const int mloc0 = branch ? m0 - BB : m0;
    const float* e = (branch ? tail_e : head_e) + (size_t)mloc0 * DD;
    const int* idx = branch ? tail_idx : head_idx;

    float acc[1][4][4];
#pragma unroll
    for (int nf = 0; nf < 4; nf++)
#pragma unroll
        for (int v = 0; v < 4; v++) acc[0][nf][v] = 0.f;

    wo_core<32>(e, sk, dsm, acc);

    const int warp = threadIdx.x >> 5, lane = threadIdx.x & 31;
    const int wm = warp >> 2, wn = warp & 3;
    const int rloc = mloc0 + wm * 16 + (lane >> 2);
    const int cbase = wn * 32 + (lane & 3) * 2;

    int i0 = d_rank[idx[rloc]], i1 = d_rank[idx[rloc + 8]];
    const float* S0 = d_S + (size_t)i0 * OO;
    const float* S1 = d_S + (size_t)i1 * OO;
    float* o0 = out + ((size_t)branch * BB + rloc) * OO;
    float* o1 = o0 + 8 * OO;
#pragma unroll
    for (int nf = 0; nf < 4; nf++) {
        int cc = cbase + nf * 8;
        float2 s0 = *(const float2*)(S0 + cc);
        float2 s1 = *(const float2*)(S1 + cc);
        *(float2*)(o0 + cc) = make_float2(acc[0][nf][0] + s0.x,
                                          acc[0][nf][1] + s0.y);
        *(float2*)(o1 + cc) = make_float2(acc[0][nf][2] + s1.x,
                                          acc[0][nf][3] + s1.y);
    }
}

// ---------------------------------------------------------------------------
extern "C" void kernel_launch(void* const* d_in, const int* in_sizes, int n_in,
                              void* d_out, int out_size)
{
    const float* emb  = (const float*)d_in[0];
    const int*   hidx = (const int*)  d_in[1];
    const float* he   = (const float*)d_in[2];
    const int*   tidx = (const int*)  d_in[3];
    const float* te   = (const float*)d_in[4];
    const float* adj  = (const float*)d_in[5];
    const float* relk = (const float*)d_in[6];
    const float* sk   = (const float*)d_in[7];
    float* out = (float*)d_out;

    cudaFuncSetAttribute(s_gemm, cudaFuncAttributeMaxDynamicSharedMemorySize, SG_SMEM);
    cudaFuncSetAttribute(w_gemm, cudaFuncAttributeMaxDynamicSharedMemorySize, W_SMEM);
    cudaFuncSetAttribute(out_gemm, cudaFuncAttributeMaxDynamicSharedMemorySize, O_SMEM);

    // 0) compact unique referenced nodes: list/rank/count
    prep_kernel<<<1, 1024>>>(hidx, tidx);
    // 1) W[r] = E @ K[r]   (fp16 mma, fp32 acc)
    w_gemm<<<dim3(NN / 128, RR), 256, W_SMEM>>>(emb, relk);
    // 2) Spart[z][rank] = sum_r adj_r[list[rank]] @ W_r over z's k-range
    s_gemm<<<dim3(NN / BM, ZSPLIT), 256, SG_SMEM>>>(adj);
    // 3) S = sum_z Spart[z]  (ranks < count only)
    reduce_kernel<<<NN * OO / (512 * 4), 512>>>();
    // 4) out = [he;te] @ SK + gather(S, rank[idx])
    out_gemm<<<2 * BB / 32, 256, O_SMEM>>>(he, te, hidx, tidx, sk, out);
}

// round 15
// speedup vs baseline: 1.5340x; 1.5340x over previous
#include <cuda_runtime.h>
#include <cuda_fp16.h>
#include <cstdint>

#define NN 4096   // nodes
#define DD 128    // embed dim
#define RR 8      // relations
#define OO 128    // out dim
#define BB 4096   // batch
#define ZSPLIT 16 // k-splits in s_gemm (448 active work units -> good balance)

// Scratch: W[r][n][o] = (E @ K[r])[n][o], fp16, 8 MB.
__device__ __half d_W16[RR * (size_t)NN * OO];
// Scratch: partial S per k-split (rank-major), fp32, 32 MB.
__device__ float d_Spart[ZSPLIT * (size_t)NN * OO];
// Scratch: S[rank][o], fp32, 2 MB.
__device__ float d_S[(size_t)NN * OO];
// Compaction of referenced nodes:
__device__ int d_list[NN];    // rank -> node (padded with 0)
__device__ int d_rank[NN];    // node -> rank (valid for referenced nodes)
__device__ int d_count;       // number of unique referenced nodes

// ---------------------------------------------------------------------------
// MMA helpers
// ---------------------------------------------------------------------------
__device__ __forceinline__ uint32_t smaddr(const void* p) {
    return (uint32_t)__cvta_generic_to_shared(p);
}
__device__ __forceinline__ void ldsm_x4(uint32_t (&r)[4], uint32_t addr) {
    asm volatile("ldmatrix.sync.aligned.m8n8.x4.shared.b16 {%0,%1,%2,%3}, [%4];"
        : "=r"(r[0]), "=r"(r[1]), "=r"(r[2]), "=r"(r[3]) : "r"(addr));
}
__device__ __forceinline__ void ldsm_x4t(uint32_t (&r)[4], uint32_t addr) {
    asm volatile("ldmatrix.sync.aligned.m8n8.x4.trans.shared.b16 {%0,%1,%2,%3}, [%4];"
        : "=r"(r[0]), "=r"(r[1]), "=r"(r[2]), "=r"(r[3]) : "r"(addr));
}
__device__ __forceinline__ void mma_16816(float (&c)[4], const uint32_t (&a)[4],
                                          const uint32_t b0, const uint32_t b1) {
    asm volatile(
        "mma.sync.aligned.m16n8k16.row.col.f32.f16.f16.f32 "
        "{%0,%1,%2,%3}, {%4,%5,%6,%7}, {%8,%9}, {%0,%1,%2,%3};"
        : "+f"(c[0]), "+f"(c[1]), "+f"(c[2]), "+f"(c[3])
        : "r"(a[0]), "r"(a[1]), "r"(a[2]), "r"(a[3]), "r"(b0), "r"(b1));
}
__device__ __forceinline__ void cpa16(uint32_t s, const void* g) {
    asm volatile("cp.async.cg.shared.global [%0], [%1], 16;" :: "r"(s), "l"(g));
}
#define CPA_COMMIT() asm volatile("cp.async.commit_group;" ::: "memory")
#define CPA_WAIT0()  asm volatile("cp.async.wait_group 0;" ::: "memory")

// ---------------------------------------------------------------------------
// Kernel P: mark referenced nodes, prefix-scan, compact. 1 CTA, 1024 thr.
// ---------------------------------------------------------------------------
__global__ __launch_bounds__(1024) void prep_kernel(
    const int* __restrict__ hidx, const int* __restrict__ tidx)
{
    __shared__ int fl[NN];        // 16 KB
    __shared__ int wsum[32];
    const int t = threadIdx.x;
    const int lane = t & 31, wid = t >> 5;

    ((int4*)fl)[t] = make_int4(0, 0, 0, 0);
    __syncthreads();
#pragma unroll
    for (int j = 0; j < 4; j++) {
        int id = t + j * 1024;
        fl[hidx[id]] = 1;
        fl[tidx[id]] = 1;
    }
    __syncthreads();

    int f[4], s = 0;
#pragma unroll
    for (int j = 0; j < 4; j++) { f[j] = fl[t * 4 + j]; s += f[j]; }

    int incl = s;
#pragma unroll
    for (int off = 1; off < 32; off <<= 1) {
        int v = __shfl_up_sync(0xffffffffu, incl, off);
        if (lane >= off) incl += v;
    }
    if (lane == 31) wsum[wid] = incl;
    __syncthreads();
    if (wid == 0) {
        int w = wsum[lane];
#pragma unroll
        for (int off = 1; off < 32; off <<= 1) {
            int v = __shfl_up_sync(0xffffffffu, w, off);
            if (lane >= off) w += v;
        }
        wsum[lane] = w;
    }
    __syncthreads();

    int run = (wid ? wsum[wid - 1] : 0) + incl - s;
#pragma unroll
    for (int j = 0; j < 4; j++) {
        if (f[j]) {
            int n = t * 4 + j;
            d_list[run] = n;
            d_rank[n] = run;
            run++;
        }
    }
    const int total = wsum[31];
    if (t == 0) d_count = total;
    for (int i = total + t; i < NN; i += 1024) d_list[i] = 0;
}

// ---------------------------------------------------------------------------
// Single-shot MROWSx128x128 fp16 MMA core (w_gemm / out_gemm).
// ---------------------------------------------------------------------------
#define STR 136                       // halves per smem row (128 + 8 pad)

template<int MROWS>
__device__ __forceinline__ void wo_core(
    const float* __restrict__ Ag, const float* __restrict__ Bg,
    char* dsm, float (&acc)[MROWS / 32][4][4])
{
    constexpr int MF = MROWS / 32;
    const int t = threadIdx.x;
    const uint32_t sb = smaddr(dsm);
    char* As = dsm;
    char* Bs = dsm + MROWS * STR * 2;
    const uint32_t AOFF = sb, BOFF = sb + MROWS * STR * 2;

#pragma unroll
    for (int j = 0; j < MROWS / 8; j++) {
        int id = t + j * 256;
        int row = id >> 5, c4 = id & 31;
        float4 v = *(const float4*)(Ag + (size_t)row * 128 + c4 * 4);
        __half2 h0 = __floats2half2_rn(v.x, v.y);
        __half2 h1 = __floats2half2_rn(v.z, v.w);
        uint2 u; u.x = *(uint32_t*)&h0; u.y = *(uint32_t*)&h1;
        *(uint2*)(As + row * STR * 2 + c4 * 8) = u;
    }
#pragma unroll
    for (int j = 0; j < 16; j++) {
        int id = t + j * 256;
        int row = id >> 5, c4 = id & 31;
        float4 v = *(const float4*)(Bg + (size_t)row * 128 + c4 * 4);
        __half2 h0 = __floats2half2_rn(v.x, v.y);
        __half2 h1 = __floats2half2_rn(v.z, v.w);
        uint2 u; u.x = *(uint32_t*)&h0; u.y = *(uint32_t*)&h1;
        *(uint2*)(Bs + row * STR * 2 + c4 * 8) = u;
    }
    __syncthreads();

    const int warp = t >> 5, lane = t & 31;
    const int wm = warp >> 2, wn = warp & 3;

    uint32_t a_off[MF], b_off[2];
#pragma unroll
    for (int mf = 0; mf < MF; mf++) {
        int row = wm * (MROWS / 2) + mf * 16 + (lane & 15);
        int col = ((lane >> 4) << 3);
        a_off[mf] = (uint32_t)(row * STR * 2 + col * 2);
    }
#pragma unroll
    for (int nf2 = 0; nf2 < 2; nf2++) {
        int row = (lane & 15);
        int col = wn * 32 + nf2 * 16 + ((lane >> 4) << 3);
        b_off[nf2] = (uint32_t)(row * STR * 2 + col * 2);
    }

#pragma unroll
    for (int ks = 0; ks < 8; ks++) {
        uint32_t af[MF][4], bf[2][4];
#pragma unroll
        for (int mf = 0; mf < MF; mf++)
            ldsm_x4(af[mf], AOFF + a_off[mf] + ks * 32);
#pragma unroll
        for (int nf2 = 0; nf2 < 2; nf2++)
            ldsm_x4t(bf[nf2], BOFF + b_off[nf2] + ks * 16 * STR * 2);
#pragma unroll
        for (int mf = 0; mf < MF; mf++)
#pragma unroll
            for (int nf = 0; nf < 4; nf++)
                mma_16816(acc[mf][nf], af[mf], bf[nf >> 1][(nf & 1) * 2],
                          bf[nf >> 1][(nf & 1) * 2 + 1]);
    }
}

// ---------------------------------------------------------------------------
// Kernel 1: W16[r] = fp16(E @ K[r]).  grid (32 m-tiles, 8 relations), 256 thr.
// ---------------------------------------------------------------------------
#define W_SMEM (2 * 128 * STR * 2)   // 69632 B

__global__ __launch_bounds__(256, 2) void w_gemm(
    const float* __restrict__ emb, const float* __restrict__ relk)
{
    extern __shared__ __align__(128) char dsm[];
    const int m0 = blockIdx.x * 128;
    const int r = blockIdx.y;

    float acc[4][4][4];
#pragma unroll
    for (int mf = 0; mf < 4; mf++)
#pragma unroll
        for (int nf = 0; nf < 4; nf++)
#pragma unroll
            for (int v = 0; v < 4; v++) acc[mf][nf][v] = 0.f;

    wo_core<128>(emb + (size_t)m0 * DD, relk + (size_t)r * DD * OO, dsm, acc);

    const int warp = threadIdx.x >> 5, lane = threadIdx.x & 31;
    const int wm = warp >> 2, wn = warp & 3;
    __half* Wr = d_W16 + (size_t)r * NN * OO;
    const int rbase = m0 + wm * 64 + (lane >> 2);
    const int cbase = wn * 32 + (lane & 3) * 2;
#pragma unroll
    for (int mf = 0; mf < 4; mf++)
#pragma unroll
        for (int nf = 0; nf < 4; nf++) {
            int rr = rbase + mf * 16, cc = cbase + nf * 8;
            *(__half2*)(Wr + (size_t)rr * OO + cc) =
                __floats2half2_rn(acc[mf][nf][0], acc[mf][nf][1]);
            *(__half2*)(Wr + (size_t)(rr + 8) * OO + cc) =
                __floats2half2_rn(acc[mf][nf][2], acc[mf][nf][3]);
        }
}

// ---------------------------------------------------------------------------
// Kernel 2: Spart[z][rank][o] = sum_r sum_{k in z} adj[r, list[rank], k] W[r][k][o]
// Row-gathered A; tiles beyond d_count exit early (CTA-uniform guard).
// grid (32 m-tiles, 16 z-splits) = 448 active units over 296 slots, 256 thr.
// ---------------------------------------------------------------------------
#define BM 128
#define BK 64
#define KRANGE (NN / ZSPLIT)      // 256 k per CTA per relation
#define QITERS (RR * KRANGE / BK) // 32 chunks
#define ASTR (BK + 8)
#define BSTR (OO + 8)
#define A_STAGE (BM * ASTR * 2)   // 18432 B
#define B_STAGE (BK * BSTR * 2)   // 17408 B
#define SG_SMEM (2 * A_STAGE + 2 * B_STAGE)   // 71680 B

__global__ __launch_bounds__(256, 2) void s_gemm(const float* __restrict__ adj)
{
    const int m0 = blockIdx.x * BM;
    if (m0 >= d_count) return;                     // tile fully past unique rows

    extern __shared__ __align__(128) char dsm[];
    __shared__ int rows_s[BM];
    const uint32_t sb = smaddr(dsm);
    const int t = threadIdx.x;
    const int z = blockIdx.y;
    const int kz = z * KRANGE;

    if (t < BM) rows_s[t] = d_list[m0 + t];
    __syncthreads();

    const uint32_t AOFF[2] = { sb, sb + A_STAGE };
    char* const ABASE[2] = { dsm, dsm + A_STAGE };
    const uint32_t BOFF[2] = { sb + 2 * A_STAGE, sb + 2 * A_STAGE + B_STAGE };

    const float* aptr[8]; uint32_t ast[8];
#pragma unroll
    for (int j = 0; j < 8; j++) {
        int id = t + j * 256;
        int arow = id >> 4, ac4 = id & 15;
        aptr[j] = adj + (size_t)rows_s[arow] * NN + kz + ac4 * 4;
        ast[j] = (uint32_t)(arow * ASTR * 2 + ac4 * 8);
    }
    const __half* bgp[4]; uint32_t bst[4];
#pragma unroll
    for (int j = 0; j < 4; j++) {
        int id = t + j * 256;
        int brow = id >> 4, bc8 = id & 15;
        bgp[j] = d_W16 + (size_t)(kz + brow) * OO + bc8 * 8;
        bst[j] = (uint32_t)(brow * BSTR * 2 + bc8 * 16);
    }

    const int warp = t >> 5, lane = t & 31;
    const int wm = warp >> 2, wn = warp & 3;

    float acc[4][4][4];
#pragma unroll
    for (int mf = 0; mf < 4; mf++)
#pragma unroll
        for (int nf = 0; nf < 4; nf++)
#pragma unroll
            for (int v = 0; v < 4; v++) acc[mf][nf][v] = 0.f;

    uint32_t a_off[4], b_off[2];
#pragma unroll
    for (int mf = 0; mf < 4; mf++) {
        int row = wm * 64 + mf * 16 + (lane & 15);
        int col = ((lane >> 4) << 3);
        a_off[mf] = (uint32_t)(row * ASTR * 2 + col * 2);
    }
#pragma unroll
    for (int nf2 = 0; nf2 < 2; nf2++) {
        int row = (lane & 15);
        int col = wn * 32 + nf2 * 16 + ((lane >> 4) << 3);
        b_off[nf2] = (uint32_t)(row * BSTR * 2 + col * 2);
    }

    // per-chunk uniform offsets: q -> (r = q>>2, kc = q&3)
    auto QA = [](int q) -> size_t {
        return ((size_t)(q >> 2) * (size_t)NN * NN) + (size_t)(q & 3) * BK;
    };
    auto QB = [](int q) -> size_t {
        return ((size_t)(q >> 2) * (size_t)NN * OO) + (size_t)(q & 3) * BK * OO;
    };

    float4 areg[8];

    // prologue: chunk 0 -> stage 0
#pragma unroll
    for (int j = 0; j < 8; j++) areg[j] = *(const float4*)aptr[j];
#pragma unroll
    for (int j = 0; j < 8; j++) {
        __half2 h0 = __floats2half2_rn(areg[j].x, areg[j].y);
        __half2 h1 = __floats2half2_rn(areg[j].z, areg[j].w);
        uint2 u; u.x = *(uint32_t*)&h0; u.y = *(uint32_t*)&h1;
        *(uint2*)(ABASE[0] + ast[j]) = u;
    }
#pragma unroll
    for (int j = 0; j < 4; j++) cpa16(BOFF[0] + bst[j], bgp[j]);
    CPA_COMMIT();
    {
        const size_t o1 = QA(1);
#pragma unroll
        for (int j = 0; j < 8; j++) areg[j] = *(const float4*)(aptr[j] + o1);
    }
    CPA_WAIT0();
    __syncthreads();

    for (int q = 0; q < QITERS; q++) {
        const int s = q & 1, ns = s ^ 1;

        if (q + 1 < QITERS) {
#pragma unroll
            for (int j = 0; j < 8; j++) {
                __half2 h0 = __floats2half2_rn(areg[j].x, areg[j].y);
                __half2 h1 = __floats2half2_rn(areg[j].z, areg[j].w);
                uint2 u; u.x = *(uint32_t*)&h0; u.y = *(uint32_t*)&h1;
                *(uint2*)(ABASE[ns] + ast[j]) = u;
            }
            const size_t ob = QB(q + 1);
#pragma unroll
            for (int j = 0; j < 4; j++) cpa16(BOFF[ns] + bst[j], bgp[j] + ob);
            CPA_COMMIT();
        }
        if (q + 2 < QITERS) {
            const size_t oa = QA(q + 2);
#pragma unroll
            for (int j = 0; j < 8; j++) areg[j] = *(const float4*)(aptr[j] + oa);
        }

#pragma unroll
        for (int ks = 0; ks < 4; ks++) {
            uint32_t af[4][4], bf[2][4];
#pragma unroll
            for (int mf = 0; mf < 4; mf++)
                ldsm_x4(af[mf], AOFF[s] + a_off[mf] + ks * 32);
#pragma unroll
            for (int nf2 = 0; nf2 < 2; nf2++)
                ldsm_x4t(bf[nf2], BOFF[s] + b_off[nf2] + ks * 16 * BSTR * 2);
#pragma unroll
            for (int mf = 0; mf < 4; mf++)
#pragma unroll
                for (int nf = 0; nf < 4; nf++)
                    mma_16816(acc[mf][nf], af[mf], bf[nf >> 1][(nf & 1) * 2],
                              bf[nf >> 1][(nf & 1) * 2 + 1]);
        }

        if (q + 1 < QITERS) CPA_WAIT0();
        __syncthreads();
    }

    float* Sp = d_Spart + (size_t)z * NN * OO;
    const int rbase = m0 + wm * 64 + (lane >> 2);
    const int cbase = wn * 32 + (lane & 3) * 2;
#pragma unroll
    for (int mf = 0; mf < 4; mf++)
#pragma unroll
        for (int nf = 0; nf < 4; nf++) {
            int rr = rbase + mf * 16, cc = cbase + nf * 8;
            *(float2*)(Sp + (size_t)rr * OO + cc) =
                make_float2(acc[mf][nf][0], acc[mf][nf][1]);
            *(float2*)(Sp + (size_t)(rr + 8) * OO + cc) =
                make_float2(acc[mf][nf][2], acc[mf][nf][3]);
        }
}

// ---------------------------------------------------------------------------
// Kernel 3: S[rank] = sum_z Spart[z][rank] for rank < count.
// ---------------------------------------------------------------------------
__global__ __launch_bounds__(512) void reduce_kernel()
{
    const size_t i = (size_t)blockIdx.x * 512 + threadIdx.x;   // float4 index
    if ((int)(i >> 5) >= d_count) return;                      // 32 float4/row
    const float4* p = (const float4*)d_Spart + i;
    float4 s = p[0];
#pragma unroll
    for (int zz = 1; zz < ZSPLIT; zz++) {
        float4 v = p[(size_t)zz * (NN * OO / 4)];
        s.x += v.x; s.y += v.y; s.z += v.z; s.w += v.w;
    }
    ((float4*)d_S)[i] = s;
}

// ---------------------------------------------------------------------------
// Kernel 4: out[m][o] = ([he;te] @ SK)[m][o] + S[rank[idx[m]]][o]
// 32-row tiles: grid 256 CTAs, 256 threads.
// ---------------------------------------------------------------------------
#define O_SMEM ((32 + 128) * STR * 2)   // 43520 B

__global__ __launch_bounds__(256) void out_gemm(
    const float* __restrict__ head_e, const float* __restrict__ tail_e,
    const int* __restrict__ head_idx, const int* __restrict__ tail_idx,
    const float* __restrict__ sk, float* __restrict__ out)
{
    extern __shared__ __align__(128) char dsm[];
    const int m0 = blockIdx.x * 32;
    const int branch = (m0 >= BB);
    const int mloc0 = branch ? m0 - BB : m0;
    const float* e = (branch ? tail_e : head_e) + (size_t)mloc0 * DD;
    const int* idx = branch ? tail_idx : head_idx;

    float acc[1][4][4];
#pragma unroll
    for (int nf = 0; nf < 4; nf++)
#pragma unroll
        for (int v = 0; v < 4; v++) acc[0][nf][v] = 0.f;

    wo_core<32>(e, sk, dsm, acc);

    const int warp = threadIdx.x >> 5, lane = threadIdx.x & 31;
    const int wm = warp >> 2, wn = warp & 3;
    const int rloc = mloc0 + wm * 16 + (lane >> 2);
    const int cbase = wn * 32 + (lane & 3) * 2;

    int i0 = d_rank[idx[rloc]], i1 = d_rank[idx[rloc + 8]];
    const float* S0 = d_S + (size_t)i0 * OO;
    const float* S1 = d_S + (size_t)i1 * OO;
    float* o0 = out + ((size_t)branch * BB + rloc) * OO;
    float* o1 = o0 + 8 * OO;
#pragma unroll
    for (int nf = 0; nf < 4; nf++) {
        int cc = cbase + nf * 8;
        float2 s0 = *(const float2*)(S0 + cc);
        float2 s1 = *(const float2*)(S1 + cc);
        *(float2*)(o0 + cc) = make_float2(acc[0][nf][0] + s0.x,
                                          acc[0][nf][1] + s0.y);
        *(float2*)(o1 + cc) = make_float2(acc[0][nf][2] + s1.x,
                                          acc[0][nf][3] + s1.y);
    }
}

// ---------------------------------------------------------------------------
extern "C" void kernel_launch(void* const* d_in, const int* in_sizes, int n_in,
                              void* d_out, int out_size)
{
    const float* emb  = (const float*)d_in[0];
    const int*   hidx = (const int*)  d_in[1];
    const float* he   = (const float*)d_in[2];
    const int*   tidx = (const int*)  d_in[3];
    const float* te   = (const float*)d_in[4];
    const float* adj  = (const float*)d_in[5];
    const float* relk = (const float*)d_in[6];
    const float* sk   = (const float*)d_in[7];
    float* out = (float*)d_out;

    cudaFuncSetAttribute(s_gemm, cudaFuncAttributeMaxDynamicSharedMemorySize, SG_SMEM);
    cudaFuncSetAttribute(w_gemm, cudaFuncAttributeMaxDynamicSharedMemorySize, W_SMEM);
    cudaFuncSetAttribute(out_gemm, cudaFuncAttributeMaxDynamicSharedMemorySize, O_SMEM);

    // 0) compact unique referenced nodes: list/rank/count
    prep_kernel<<<1, 1024>>>(hidx, tidx);
    // 1) W[r] = E @ K[r]   (fp16 mma, fp32 acc)
    w_gemm<<<dim3(NN / 128, RR), 256, W_SMEM>>>(emb, relk);
    // 2) Spart[z][rank] = sum_r adj_r[list[rank]] @ W_r over z's k-range
    s_gemm<<<dim3(NN / BM, ZSPLIT), 256, SG_SMEM>>>(adj);
    // 3) S = sum_z Spart[z]  (ranks < count only)
    reduce_kernel<<<NN * OO / (512 * 4), 512>>>();
    // 4) out = [he;te] @ SK + gather(S, rank[idx])
    out_gemm<<<2 * BB / 32, 256, O_SMEM>>>(he, te, hidx, tidx, sk, out);
}